// round 1
// baseline (speedup 1.0000x reference)
#include <cuda_runtime.h>

#define NN 500000
#define ND 128
#define NH 64
#define NG 16384

#define TB 256          // threads per block (8 warps)
#define NB 128          // nodes per block
#define KC 16           // k-chunk staged in shared
#define XPITCH 260      // words per k-pair plane (bank-conflict-free pad)

typedef unsigned long long ull;

__device__ int g_batch_is64;

// batch is jnp.int64 in the reference but jax w/o x64 silently emits int32.
// If stored as int64, every odd 32-bit word is the (zero) high half.
// Word 499999 is the high half of element 249999 (int64) or batch[499999]
// (int32, ~16383 and certainly nonzero for sorted random data).
__global__ void detect_kernel(const int* __restrict__ w) {
    g_batch_is64 = (w[NN - 1] == 0) ? 1 : 0;
}

__global__ void zero_kernel(float* __restrict__ p, int n) {
    int i = blockIdx.x * blockDim.x + threadIdx.x;
    if (i < n) p[i] = 0.0f;
}

__device__ __forceinline__ void fma2(ull& d, ull a, ull b) {
    asm("fma.rn.f32x2 %0, %1, %2, %0;" : "+l"(d) : "l"(a), "l"(b));
}

__global__ __launch_bounds__(TB, 2)
void mlp_kernel(const float* __restrict__ X,
                const float* __restrict__ aein,
                const void*  __restrict__ batch,
                const float* __restrict__ W1,
                const float* __restrict__ b1,
                const float* __restrict__ W2,
                const float* __restrict__ b2,
                float* __restrict__ out)
{
    // ws: W1 in (k-pair, j, parity) layout: word = (k>>1)*128 + j*2 + (k&1)
    __shared__ float ws[NH * ND];              // 32 KB
    // xs: X chunk in (k-pair, node, parity) planes; aliased as reduce buf later
    __shared__ float xs[(KC / 2) * XPITCH];    // ~8.1 KB

    const int tid   = threadIdx.x;
    const int lane  = tid & 31;
    const int wid   = tid >> 5;
    const int node0 = blockIdx.x * NB;
    const int jbase = wid * 8;                 // warp owns 8 output columns

    // Stage W1 once (L2-resident after first wave)
    for (int idx = tid; idx < NH * ND; idx += TB) {
        int j = idx >> 7;        // row of W1 [64][128]
        int k = idx & 127;
        ws[(k >> 1) * 128 + j * 2 + (k & 1)] = W1[idx];
    }

    // 4 nodes x 8 cols of f32x2 accumulators (lo = even-k sum, hi = odd-k sum)
    ull acc[4][8];
#pragma unroll
    for (int i = 0; i < 4; i++)
#pragma unroll
        for (int jj = 0; jj < 8; jj++) acc[i][jj] = 0ULL;

    for (int kc = 0; kc < ND; kc += KC) {
        __syncthreads();
        // Load 128 nodes x 16 k (coalesced float4), store transposed k-pair planes
#pragma unroll
        for (int q = 0; q < 2; q++) {
            int f4 = tid + q * TB;           // 0..511
            int n  = f4 >> 2;                // node local (4 float4 per node)
            int kk = (f4 & 3) * 4;           // k within chunk
            int gn = node0 + n;
            float4 v = make_float4(0.f, 0.f, 0.f, 0.f);
            if (gn < NN) v = *(const float4*)(X + (size_t)gn * ND + kc + kk);
            int kp = kk >> 1;                // local k-pair plane (even)
            *(float2*)(xs + kp * XPITCH + n * 2)       = make_float2(v.x, v.y);
            *(float2*)(xs + (kp + 1) * XPITCH + n * 2) = make_float2(v.z, v.w);
        }
        __syncthreads();

#pragma unroll
        for (int kp = 0; kp < KC / 2; kp++) {
            const int kpg = (kc >> 1) + kp;
            const float* wsrow = ws + kpg * 128 + jbase * 2;
            ulonglong2 u0 = *(const ulonglong2*)(wsrow + 0);
            ulonglong2 u1 = *(const ulonglong2*)(wsrow + 4);
            ulonglong2 u2 = *(const ulonglong2*)(wsrow + 8);
            ulonglong2 u3 = *(const ulonglong2*)(wsrow + 12);
            ull wv[8] = {u0.x, u0.y, u1.x, u1.y, u2.x, u2.y, u3.x, u3.y};
#pragma unroll
            for (int i = 0; i < 4; i++) {
                ull xv = *(const ull*)(xs + kp * XPITCH + (lane + 32 * i) * 2);
#pragma unroll
                for (int jj = 0; jj < 8; jj++) fma2(acc[i][jj], xv, wv[jj]);
            }
        }
    }

    // Epilogue: h = silu(acc.lo + acc.hi + b1[j]); partial = sum_j h * W2[j]
    float b1r[8], w2r[8];
#pragma unroll
    for (int jj = 0; jj < 8; jj++) {
        b1r[jj] = b1[jbase + jj];
        w2r[jj] = W2[jbase + jj];
    }
    float part[4];
#pragma unroll
    for (int i = 0; i < 4; i++) {
        float p = 0.f;
#pragma unroll
        for (int jj = 0; jj < 8; jj++) {
            float2 a = *(float2*)&acc[i][jj];
            float h = a.x + a.y + b1r[jj];
            float s = h / (1.0f + __expf(-h));   // silu
            p += s * w2r[jj];
        }
        part[i] = p;
    }

    __syncthreads();
    float* red = xs;   // alias: 8 warps x 128 nodes = 4 KB <= sizeof(xs)
#pragma unroll
    for (int i = 0; i < 4; i++)
        red[wid * NB + lane + 32 * i] = part[i];
    __syncthreads();

    if (tid < NB) {
        int gn = node0 + tid;
        if (gn < NN) {
            float e = b2[0] + aein[gn];
#pragma unroll
            for (int w = 0; w < 8; w++) e += red[w * NB + tid];
            out[gn] = e;
            int g;
            if (g_batch_is64) g = (int)((const long long*)batch)[gn];
            else              g = ((const int*)batch)[gn];
            atomicAdd(out + NN + g, e);
        }
    }
}

extern "C" void kernel_launch(void* const* d_in, const int* in_sizes, int n_in,
                              void* d_out, int out_size) {
    const float* X     = (const float*)d_in[0];
    const float* aein  = (const float*)d_in[1];
    const void*  batch = d_in[2];
    const float* W1    = (const float*)d_in[3];
    const float* b1    = (const float*)d_in[4];
    const float* W2    = (const float*)d_in[5];
    const float* b2    = (const float*)d_in[6];
    float* out = (float*)d_out;

    detect_kernel<<<1, 1>>>((const int*)batch);
    zero_kernel<<<(NG + 255) / 256, 256>>>(out + NN, NG);
    mlp_kernel<<<(NN + NB - 1) / NB, TB>>>(X, aein, batch, W1, b1, W2, b2, out);
}

// round 3
// speedup vs baseline: 1.2388x; 1.2388x over previous
#include <cuda_runtime.h>
#include <mma.h>
#include <cstdint>

using namespace nvcuda;

#define NN 500000
#define ND 128
#define NH 64
#define NG 16384
#define NB 128             // nodes per CTA
#define TB 256             // threads per CTA (8 warps)

#define APITCH 132         // floats per X row in smem (pad for bank rotation)
#define WPITCH 132         // floats per W1 row in smem
#define CPITCH 68          // floats per C row in smem
#define A_FLOATS (NB * APITCH)      // 16896
#define W_FLOATS (NH * WPITCH)      //  8448
#define SMEM_DYN ((A_FLOATS + W_FLOATS) * 4)   // 101376 B

__device__ int g_batch_is64;

// Zero graph-energy slots; detect batch dtype. Word NN-1 is the zero high
// half of element (NN/2)-1 iff batch was stored as int64.
__global__ void init_kernel(float* __restrict__ out, const int* __restrict__ bw) {
    int i = blockIdx.x * blockDim.x + threadIdx.x;
    if (i < NG) out[NN + i] = 0.0f;
    if (i == 0) g_batch_is64 = (bw[NN - 1] == 0) ? 1 : 0;
}

// Round fp32 bits to tf32 (RN): add half-ulp of the 10-bit mantissa.
__device__ __forceinline__ uint4 rnd4(uint4 v) {
    v.x += 0x1000u; v.y += 0x1000u; v.z += 0x1000u; v.w += 0x1000u;
    return v;
}

__global__ __launch_bounds__(TB, 2)
void mlp_kernel(const float* __restrict__ X,
                const float* __restrict__ aein,
                const void*  __restrict__ batch,
                const float* __restrict__ W1,
                const float* __restrict__ b1,
                const float* __restrict__ W2,
                const float* __restrict__ b2,
                float* __restrict__ out)
{
    extern __shared__ float sm[];
    float* As = sm;                 // X tile  [128][APITCH]
    float* Ws = sm + A_FLOATS;      // W1 tile [64][WPITCH]
    __shared__ float b1s[NH], w2s[NH];

    const int tid   = threadIdx.x;
    const int wid   = tid >> 5;
    const int node0 = blockIdx.x * NB;

    // ---- Stage X tile (coalesced float4), tf32-rounded ----
    #pragma unroll
    for (int i = tid; i < NB * (ND / 4); i += TB) {     // 4096 float4
        int row = i >> 5;
        int c4  = i & 31;
        int gn  = node0 + row;
        uint4 v = make_uint4(0u, 0u, 0u, 0u);
        if (gn < NN) v = rnd4(*(const uint4*)(X + (size_t)gn * ND + c4 * 4));
        *(uint4*)(As + row * APITCH + c4 * 4) = v;
    }
    // ---- Stage W1, tf32-rounded ----
    #pragma unroll
    for (int i = tid; i < NH * (ND / 4); i += TB) {     // 2048 float4
        int row = i >> 5;
        int c4  = i & 31;
        uint4 v = rnd4(*(const uint4*)(W1 + (size_t)row * ND + c4 * 4));
        *(uint4*)(Ws + row * WPITCH + c4 * 4) = v;
    }
    if (tid < NH) { b1s[tid] = b1[tid]; w2s[tid] = W2[tid]; }
    __syncthreads();

    // ---- Layer-1 GEMM: warp => 16 nodes x 64 cols, K in 16 steps of 8 ----
    wmma::fragment<wmma::accumulator, 16, 16, 8, float> acc[4];
    #pragma unroll
    for (int nt = 0; nt < 4; nt++) wmma::fill_fragment(acc[nt], 0.0f);

    const float* Arow = As + wid * 16 * APITCH;
    #pragma unroll
    for (int k = 0; k < ND / 8; k++) {
        wmma::fragment<wmma::matrix_a, 16, 16, 8, wmma::precision::tf32,
                       wmma::row_major> a;
        wmma::load_matrix_sync(a, Arow + k * 8, APITCH);
        #pragma unroll
        for (int nt = 0; nt < 4; nt++) {
            wmma::fragment<wmma::matrix_b, 16, 16, 8, wmma::precision::tf32,
                           wmma::col_major> b;
            // col_major: elem(k',n') at ptr[n'*ldm + k'] == W1[nt*16+n'][k*8+k']
            wmma::load_matrix_sync(b, Ws + (nt * 16) * WPITCH + k * 8, WPITCH);
            wmma::mma_sync(acc[nt], a, b, acc[nt]);
        }
    }

    // ---- Spill C to smem (aliases As; all A reads are done) ----
    __syncthreads();
    float* Cs = As;                 // [128][CPITCH]
    #pragma unroll
    for (int nt = 0; nt < 4; nt++)
        wmma::store_matrix_sync(Cs + wid * 16 * CPITCH + nt * 16, acc[nt],
                                CPITCH, wmma::mem_row_major);
    __syncthreads();

    // ---- Epilogue: silu + layer-2 + residual + segment-sum atomic ----
    if (tid < NB) {
        int gn = node0 + tid;
        if (gn < NN) {
            float e = __ldg(b2) + __ldg(aein + gn);
            const float* crow = Cs + tid * CPITCH;
            #pragma unroll
            for (int j = 0; j < NH; j++) {
                float h = crow[j] + b1s[j];
                float s = h / (1.0f + __expf(-h));
                e = fmaf(s, w2s[j], e);
            }
            out[gn] = e;
            int g;
            if (g_batch_is64) g = (int)((const long long*)batch)[gn];
            else              g = ((const int*)batch)[gn];
            atomicAdd(out + NN + g, e);
        }
    }
}

extern "C" void kernel_launch(void* const* d_in, const int* in_sizes, int n_in,
                              void* d_out, int out_size) {
    const float* X     = (const float*)d_in[0];
    const float* aein  = (const float*)d_in[1];
    const void*  batch = d_in[2];
    const float* W1    = (const float*)d_in[3];
    const float* b1    = (const float*)d_in[4];
    const float* W2    = (const float*)d_in[5];
    const float* b2    = (const float*)d_in[6];
    float* out = (float*)d_out;

    cudaFuncSetAttribute(mlp_kernel, cudaFuncAttributeMaxDynamicSharedMemorySize,
                         SMEM_DYN);

    init_kernel<<<(NG + 255) / 256, 256>>>(out, (const int*)batch);
    mlp_kernel<<<(NN + NB - 1) / NB, TB, SMEM_DYN>>>(X, aein, batch, W1, b1,
                                                     W2, b2, out);
}